// round 5
// baseline (speedup 1.0000x reference)
#include <cuda_runtime.h>
#include <cstdint>

// ---------------- problem constants ----------------
#define NW    4096
#define NTOK  64
#define CDIM  512
#define HEADS 16
#define DHEAD 32
#define MROWS (NW * NTOK)        // 262144
#define NQKV  (3 * CDIM)         // 1536

// ---------------- scratch (device globals; no allocs allowed) ----------------
__device__ float g_qkv [(size_t)MROWS * NQKV];   // 1.6 GB
__device__ float g_attn[(size_t)MROWS * CDIM];   // 512 MB
__device__ float g_bias[HEADS * NTOK * NTOK];    // 256 KB

// ---------------- tf32 helpers ----------------
__device__ __forceinline__ uint32_t f2tf32(float x) {
    uint32_t r;
    asm("cvt.rna.tf32.f32 %0, %1;" : "=r"(r) : "f"(x));
    return r;
}

__device__ __forceinline__ void mma_tf32(float d[4],
                                         uint32_t a0, uint32_t a1, uint32_t a2, uint32_t a3,
                                         uint32_t b0, uint32_t b1) {
    asm volatile(
        "mma.sync.aligned.m16n8k8.row.col.f32.tf32.tf32.f32 "
        "{%0,%1,%2,%3}, {%4,%5,%6,%7}, {%8,%9}, {%0,%1,%2,%3};\n"
        : "+f"(d[0]), "+f"(d[1]), "+f"(d[2]), "+f"(d[3])
        : "r"(a0), "r"(a1), "r"(a2), "r"(a3), "r"(b0), "r"(b1));
}

// ---------------- bias precompute: g_bias[h][i][j] = table[rel_index[i][j]][h] ----------------
__global__ void bias_kernel(const float* __restrict__ table,
                            const int* __restrict__ relidx,
                            float* __restrict__ bias_out) {
    int h = blockIdx.x;
    for (int idx = threadIdx.x; idx < NTOK * NTOK; idx += blockDim.x) {
        bias_out[h * (NTOK * NTOK) + idx] = table[relidx[idx] * HEADS + h];
    }
}

// ---------------- tf32 GEMM: C[M,N] = X[M,512] @ W[512,N] + bias[N] ----------------
#define BM 128
#define BN 128
#define BK 32
#define ASTR 36     // padded k-stride for A tile (conflict-free frag reads)
#define BSTR 136    // padded n-stride for B tile (conflict-free frag reads)
#define GEMM_SMEM ((2 * BM * ASTR + 2 * BK * BSTR) * 4)   // 71680 bytes

__global__ void __launch_bounds__(256, 2)
gemm_tf32_kernel(const float* __restrict__ X, const float* __restrict__ W,
                 const float* __restrict__ bias, float* __restrict__ C, int N) {
    extern __shared__ uint32_t smem[];
    uint32_t* As = smem;                  // [2][BM][ASTR]
    uint32_t* Bs = smem + 2 * BM * ASTR;  // [2][BK][BSTR]

    const int tid  = threadIdx.x;
    const int lane = tid & 31;
    const int warp = tid >> 5;
    const int bm = blockIdx.y * BM;
    const int bn = blockIdx.x * BN;
    const int wm = (warp >> 1) * 32;   // 4 warps along M, 32 rows each
    const int wn = (warp & 1) * 64;    // 2 warps along N, 64 cols each
    const int qr = lane >> 2;          // 0..7
    const int qc = lane & 3;           // 0..3

    // global load mapping
    const int arow = tid >> 3;           // 0..31 (rows arow + 32p)
    const int ac   = (tid & 7) << 2;     // float4 col
    const int brow = tid >> 5;           // 0..7 (rows brow + 8p)
    const int bc   = (tid & 31) << 2;

    float acc[2][8][4];
#pragma unroll
    for (int i = 0; i < 2; i++)
#pragma unroll
        for (int j = 0; j < 8; j++)
#pragma unroll
            for (int r = 0; r < 4; r++) acc[i][j][r] = 0.f;

    const float* Xp = X + (size_t)bm * CDIM;
    const float* Wp = W + bn;

    float4 ar[4], br[4];
    // prologue: tile k=0
#pragma unroll
    for (int p = 0; p < 4; p++) {
        ar[p] = *(const float4*)(Xp + (size_t)(arow + 32 * p) * CDIM + ac);
        br[p] = *(const float4*)(Wp + (size_t)(brow + 8 * p) * N + bc);
    }
#pragma unroll
    for (int p = 0; p < 4; p++) {
        uint32_t* d = As + (arow + 32 * p) * ASTR + ac;
        d[0] = f2tf32(ar[p].x); d[1] = f2tf32(ar[p].y);
        d[2] = f2tf32(ar[p].z); d[3] = f2tf32(ar[p].w);
        uint32_t* e = Bs + (brow + 8 * p) * BSTR + bc;
        e[0] = f2tf32(br[p].x); e[1] = f2tf32(br[p].y);
        e[2] = f2tf32(br[p].z); e[3] = f2tf32(br[p].w);
    }
    __syncthreads();

    const int NKT = CDIM / BK;   // 16
    for (int kt = 0; kt < NKT; kt++) {
        const int buf = kt & 1;
        if (kt + 1 < NKT) {
            const int k0 = (kt + 1) * BK;
#pragma unroll
            for (int p = 0; p < 4; p++) {
                ar[p] = *(const float4*)(Xp + (size_t)(arow + 32 * p) * CDIM + k0 + ac);
                br[p] = *(const float4*)(Wp + (size_t)(k0 + brow + 8 * p) * N + bc);
            }
        }
        const uint32_t* ab = As + buf * BM * ASTR;
        const uint32_t* bb = Bs + buf * BK * BSTR;
#pragma unroll
        for (int ks = 0; ks < 4; ks++) {
            uint32_t afr[2][4], bfr[8][2];
            const int c = ks * 8 + qc;
#pragma unroll
            for (int mi = 0; mi < 2; mi++) {
                const int r = wm + mi * 16 + qr;
                afr[mi][0] = ab[r * ASTR + c];
                afr[mi][1] = ab[(r + 8) * ASTR + c];
                afr[mi][2] = ab[r * ASTR + c + 4];
                afr[mi][3] = ab[(r + 8) * ASTR + c + 4];
            }
#pragma unroll
            for (int ni = 0; ni < 8; ni++) {
                const int cc = wn + ni * 8 + qr;
                bfr[ni][0] = bb[(ks * 8 + qc) * BSTR + cc];
                bfr[ni][1] = bb[(ks * 8 + 4 + qc) * BSTR + cc];
            }
#pragma unroll
            for (int mi = 0; mi < 2; mi++)
#pragma unroll
                for (int ni = 0; ni < 8; ni++)
                    mma_tf32(acc[mi][ni], afr[mi][0], afr[mi][1], afr[mi][2], afr[mi][3],
                             bfr[ni][0], bfr[ni][1]);
        }
        if (kt + 1 < NKT) {
            const int nbuf = buf ^ 1;
            uint32_t* a1 = As + nbuf * BM * ASTR;
            uint32_t* b1 = Bs + nbuf * BK * BSTR;
#pragma unroll
            for (int p = 0; p < 4; p++) {
                uint32_t* d = a1 + (arow + 32 * p) * ASTR + ac;
                d[0] = f2tf32(ar[p].x); d[1] = f2tf32(ar[p].y);
                d[2] = f2tf32(ar[p].z); d[3] = f2tf32(ar[p].w);
                uint32_t* e = b1 + (brow + 8 * p) * BSTR + bc;
                e[0] = f2tf32(br[p].x); e[1] = f2tf32(br[p].y);
                e[2] = f2tf32(br[p].z); e[3] = f2tf32(br[p].w);
            }
        }
        __syncthreads();
    }

    // epilogue: add bias, store
#pragma unroll
    for (int mi = 0; mi < 2; mi++) {
        const int row = bm + wm + mi * 16 + qr;
#pragma unroll
        for (int ni = 0; ni < 8; ni++) {
            const int col = bn + wn + ni * 8 + (qc << 1);
            const float b0v = bias[col], b1v = bias[col + 1];
            *(float2*)(C + (size_t)row * N + col) =
                make_float2(acc[mi][ni][0] + b0v, acc[mi][ni][1] + b1v);
            *(float2*)(C + (size_t)(row + 8) * N + col) =
                make_float2(acc[mi][ni][2] + b0v, acc[mi][ni][3] + b1v);
        }
    }
}

// ---------------- attention: one CTA per (window, head), 4 warps ----------------
__global__ void __launch_bounds__(128)
attn_kernel(const float* __restrict__ qkv, const float* __restrict__ mask,
            const float* __restrict__ biasg, float* __restrict__ outp) {
    __shared__ uint32_t qs[64][36];
    __shared__ uint32_t ksm[64][36];
    __shared__ uint32_t vsm[64][40];
    __shared__ uint32_t ps[4][16][68];
    __shared__ float    masks[64];

    const int b = blockIdx.x;
    const int h = blockIdx.y;
    const int tid  = threadIdx.x;
    const int lane = tid & 31;
    const int warp = tid >> 5;
    const int qr = lane >> 2;   // 0..7
    const int qc = lane & 3;    // 0..3

    // cooperative load of q,k,v for this (window, head): 64 tokens x 32 dims each
    const float* base = qkv + (size_t)b * NTOK * NQKV + h * DHEAD;
#pragma unroll
    for (int p = 0; p < 4; p++) {
        const int g = tid + 128 * p;
        const int t = g >> 3;
        const int c = (g & 7) << 2;
        const float* rowp = base + (size_t)t * NQKV + c;
        float4 qv = *(const float4*)(rowp);
        float4 kv = *(const float4*)(rowp + CDIM);
        float4 vv = *(const float4*)(rowp + 2 * CDIM);
        qs[t][c]     = f2tf32(qv.x); qs[t][c + 1] = f2tf32(qv.y);
        qs[t][c + 2] = f2tf32(qv.z); qs[t][c + 3] = f2tf32(qv.w);
        ksm[t][c]     = f2tf32(kv.x); ksm[t][c + 1] = f2tf32(kv.y);
        ksm[t][c + 2] = f2tf32(kv.z); ksm[t][c + 3] = f2tf32(kv.w);
        vsm[t][c]     = f2tf32(vv.x); vsm[t][c + 1] = f2tf32(vv.y);
        vsm[t][c + 2] = f2tf32(vv.z); vsm[t][c + 3] = f2tf32(vv.w);
    }
    if (tid < 64) masks[tid] = mask[(size_t)b * NTOK + tid];
    __syncthreads();

    // S = Q K^T for this warp's 16 rows
    const int i0 = warp * 16;
    float sacc[8][4];
#pragma unroll
    for (int nt = 0; nt < 8; nt++)
#pragma unroll
        for (int r = 0; r < 4; r++) sacc[nt][r] = 0.f;

#pragma unroll
    for (int ks = 0; ks < 4; ks++) {
        const int c = ks * 8 + qc;
        const uint32_t a0 = qs[i0 + qr][c];
        const uint32_t a1 = qs[i0 + 8 + qr][c];
        const uint32_t a2 = qs[i0 + qr][c + 4];
        const uint32_t a3 = qs[i0 + 8 + qr][c + 4];
#pragma unroll
        for (int nt = 0; nt < 8; nt++) {
            const uint32_t b0 = ksm[nt * 8 + qr][c];
            const uint32_t b1 = ksm[nt * 8 + qr][c + 4];
            mma_tf32(sacc[nt], a0, a1, a2, a3, b0, b1);
        }
    }

    // scale + bias + mask, then fragment-layout softmax (rows ra, rb per thread)
    const float scale = 0.17677669529663687f;   // 1/sqrt(32)
    const float* brow = biasg + h * (NTOK * NTOK);
    const int ra = i0 + qr;
    const int rb = ra + 8;

    float pv[8][4];
    float mA = -1e30f, mB = -1e30f;
#pragma unroll
    for (int nt = 0; nt < 8; nt++) {
        const int j = nt * 8 + (qc << 1);
        const float2 biA = *(const float2*)(brow + ra * 64 + j);
        const float2 biB = *(const float2*)(brow + rb * 64 + j);
        const float m0 = masks[j], m1 = masks[j + 1];
        pv[nt][0] = sacc[nt][0] * scale + biA.x + m0;
        pv[nt][1] = sacc[nt][1] * scale + biA.y + m1;
        pv[nt][2] = sacc[nt][2] * scale + biB.x + m0;
        pv[nt][3] = sacc[nt][3] * scale + biB.y + m1;
        mA = fmaxf(mA, fmaxf(pv[nt][0], pv[nt][1]));
        mB = fmaxf(mB, fmaxf(pv[nt][2], pv[nt][3]));
    }
#pragma unroll
    for (int off = 1; off <= 2; off <<= 1) {
        mA = fmaxf(mA, __shfl_xor_sync(0xffffffffu, mA, off));
        mB = fmaxf(mB, __shfl_xor_sync(0xffffffffu, mB, off));
    }
    float sA = 0.f, sB = 0.f;
#pragma unroll
    for (int nt = 0; nt < 8; nt++) {
        pv[nt][0] = __expf(pv[nt][0] - mA);
        pv[nt][1] = __expf(pv[nt][1] - mA);
        pv[nt][2] = __expf(pv[nt][2] - mB);
        pv[nt][3] = __expf(pv[nt][3] - mB);
        sA += pv[nt][0] + pv[nt][1];
        sB += pv[nt][2] + pv[nt][3];
    }
#pragma unroll
    for (int off = 1; off <= 2; off <<= 1) {
        sA += __shfl_xor_sync(0xffffffffu, sA, off);
        sB += __shfl_xor_sync(0xffffffffu, sB, off);
    }
    const float rAi = 1.f / sA;
    const float rBi = 1.f / sB;

    // stage normalized P (tf32) through SMEM for A-fragment relayout
#pragma unroll
    for (int nt = 0; nt < 8; nt++) {
        const int j = nt * 8 + (qc << 1);
        ps[warp][qr][j]         = f2tf32(pv[nt][0] * rAi);
        ps[warp][qr][j + 1]     = f2tf32(pv[nt][1] * rAi);
        ps[warp][qr + 8][j]     = f2tf32(pv[nt][2] * rBi);
        ps[warp][qr + 8][j + 1] = f2tf32(pv[nt][3] * rBi);
    }
    __syncwarp();

    // O = P V
    float oacc[4][4];
#pragma unroll
    for (int nt = 0; nt < 4; nt++)
#pragma unroll
        for (int r = 0; r < 4; r++) oacc[nt][r] = 0.f;

#pragma unroll
    for (int ks = 0; ks < 8; ks++) {
        const int c = ks * 8 + qc;
        const uint32_t a0 = ps[warp][qr][c];
        const uint32_t a1 = ps[warp][qr + 8][c];
        const uint32_t a2 = ps[warp][qr][c + 4];
        const uint32_t a3 = ps[warp][qr + 8][c + 4];
#pragma unroll
        for (int nt = 0; nt < 4; nt++) {
            const uint32_t b0 = vsm[ks * 8 + qc][nt * 8 + qr];
            const uint32_t b1 = vsm[ks * 8 + 4 + qc][nt * 8 + qr];
            mma_tf32(oacc[nt], a0, a1, a2, a3, b0, b1);
        }
    }

    // write [token, h*32 + d] into g_attn
    float* ob = outp + ((size_t)b * NTOK + i0) * CDIM + h * DHEAD;
#pragma unroll
    for (int nt = 0; nt < 4; nt++) {
        const int d = nt * 8 + (qc << 1);
        *(float2*)(ob + (size_t)qr * CDIM + d) = make_float2(oacc[nt][0], oacc[nt][1]);
        *(float2*)(ob + (size_t)(qr + 8) * CDIM + d) = make_float2(oacc[nt][2], oacc[nt][3]);
    }
}

// ---------------- launch ----------------
extern "C" void kernel_launch(void* const* d_in, const int* in_sizes, int n_in,
                              void* d_out, int out_size) {
    const float* x      = (const float*)d_in[0];
    const float* mask   = (const float*)d_in[1];
    const float* qkv_w  = (const float*)d_in[2];
    const float* qkv_b  = (const float*)d_in[3];
    const float* table  = (const float*)d_in[4];
    const float* proj_w = (const float*)d_in[5];
    const float* proj_b = (const float*)d_in[6];
    const int*   relidx = (const int*)d_in[7];
    float* out = (float*)d_out;

    float *p_qkv = nullptr, *p_attn = nullptr, *p_bias = nullptr;
    cudaGetSymbolAddress((void**)&p_qkv, g_qkv);
    cudaGetSymbolAddress((void**)&p_attn, g_attn);
    cudaGetSymbolAddress((void**)&p_bias, g_bias);

    cudaFuncSetAttribute(gemm_tf32_kernel,
                         cudaFuncAttributeMaxDynamicSharedMemorySize, GEMM_SMEM);

    // 1) relative-position bias gather -> [H, 64, 64]
    bias_kernel<<<HEADS, 256>>>(table, relidx, p_bias);

    // 2) QKV projection: [262144, 512] @ [512, 1536] + b
    gemm_tf32_kernel<<<dim3(NQKV / BN, MROWS / BM), 256, GEMM_SMEM>>>(
        x, qkv_w, qkv_b, p_qkv, NQKV);

    // 3) windowed attention per (window, head)
    attn_kernel<<<dim3(NW, HEADS), 128>>>(p_qkv, mask, p_bias, p_attn);

    // 4) output projection: [262144, 512] @ [512, 512] + b
    gemm_tf32_kernel<<<dim3(CDIM / BN, MROWS / BM), 256, GEMM_SMEM>>>(
        p_attn, proj_w, proj_b, out, CDIM);
}

// round 7
// speedup vs baseline: 1.0184x; 1.0184x over previous
#include <cuda_runtime.h>
#include <cstdint>

// ---------------- problem constants ----------------
#define NW    4096
#define NTOK  64
#define CDIM  512
#define HEADS 16
#define DHEAD 32
#define MROWS (NW * NTOK)        // 262144
#define NQKV  (3 * CDIM)         // 1536

// ---------------- scratch (device globals; no allocs allowed) ----------------
__device__ float g_qkv [(size_t)MROWS * NQKV];   // 1.6 GB
__device__ float g_attn[(size_t)MROWS * CDIM];   // 512 MB
__device__ float g_bias[HEADS * NTOK * NTOK];    // 256 KB

// ---------------- tf32 helpers ----------------
__device__ __forceinline__ uint32_t f2tf32(float x) {
    uint32_t r;
    asm("cvt.rna.tf32.f32 %0, %1;" : "=r"(r) : "f"(x));
    return r;
}

__device__ __forceinline__ void mma_tf32(float d[4],
                                         uint32_t a0, uint32_t a1, uint32_t a2, uint32_t a3,
                                         uint32_t b0, uint32_t b1) {
    asm volatile(
        "mma.sync.aligned.m16n8k8.row.col.f32.tf32.tf32.f32 "
        "{%0,%1,%2,%3}, {%4,%5,%6,%7}, {%8,%9}, {%0,%1,%2,%3};\n"
        : "+f"(d[0]), "+f"(d[1]), "+f"(d[2]), "+f"(d[3])
        : "r"(a0), "r"(a1), "r"(a2), "r"(a3), "r"(b0), "r"(b1));
}

__device__ __forceinline__ uint32_t smem_u32(const void* p) {
    uint32_t a;
    asm("{ .reg .u64 t; cvta.to.shared.u64 t, %1; cvt.u32.u64 %0, t; }" : "=r"(a) : "l"(p));
    return a;
}
__device__ __forceinline__ void cp16(uint32_t dst, const void* src) {
    asm volatile("cp.async.cg.shared.global [%0], [%1], 16;\n" :: "r"(dst), "l"(src));
}
#define CP_COMMIT() asm volatile("cp.async.commit_group;\n" ::: "memory")
#define CP_WAIT1()  asm volatile("cp.async.wait_group 1;\n" ::: "memory")

// ---------------- bias precompute: g_bias[h][i][j] = table[rel_index[i][j]][h] ----------------
__global__ void bias_kernel(const float* __restrict__ table,
                            const int* __restrict__ relidx,
                            float* __restrict__ bias_out) {
    int h = blockIdx.x;
    for (int idx = threadIdx.x; idx < NTOK * NTOK; idx += blockDim.x) {
        bias_out[h * (NTOK * NTOK) + idx] = table[relidx[idx] * HEADS + h];
    }
}

// ---------------- tf32 GEMM: C[M,N] = X[M,512] @ W[512,N] + bias[N] ----------------
// CTA 128x256, 8 warps in 2(M) x 4(N) grid, warp tile 64x64 (1.0 LDS.32 per mma).
// 3-stage cp.async pipeline, BK=32. SMEM holds raw fp32; cvt.rna.tf32 at fragment load.
#define BM 128
#define BN 256
#define BK 32
#define APITCH 36                         // fp32 words per A row (pad 4)
#define BPITCH 264                        // fp32 words per B row (pad 8)
#define ABYTES (BM * APITCH * 4)          // 18432
#define BBYTES (BK * BPITCH * 4)          // 33792
#define STAGE  (ABYTES + BBYTES)          // 52224
#define GEMM_SMEM (3 * STAGE)             // 156672

__global__ void __launch_bounds__(256, 1)
gemm_tf32_kernel(const float* __restrict__ X, const float* __restrict__ W,
                 const float* __restrict__ bias, float* __restrict__ C, int Ntot) {
    extern __shared__ char smem[];
    const uint32_t sbase = smem_u32(smem);

    const int tid  = threadIdx.x;
    const int lane = tid & 31;
    const int warp = tid >> 5;
    const long bm = (long)blockIdx.y * BM;
    const int  bn = blockIdx.x * BN;
    const int wm = (warp >> 2) * 64;     // 2 warps along M
    const int wn = (warp & 3) * 64;      // 4 warps along N
    const int qr = lane >> 2;            // 0..7
    const int qc = lane & 3;             // 0..3

    // fill(stage, kt): A tile [BM x BK] fp32, B tile [BK x BN] fp32, via cp.async 16B
    auto fill = [&](int st, int kt) {
        const uint32_t abase = sbase + st * STAGE;
        const uint32_t bbase = abase + ABYTES;
        const int k0 = kt * BK;
        // A: 128 rows x 8 chunks(16B) = 1024 chunks, 4 per thread
        {
            const float* Xb = X + (size_t)bm * CDIM + k0;
#pragma unroll
            for (int j = 0; j < 4; j++) {
                const int id  = tid + 256 * j;
                const int row = id >> 3;
                const int c   = id & 7;
                cp16(abase + row * (APITCH * 4) + c * 16,
                     Xb + (size_t)row * CDIM + c * 4);
            }
        }
        // B: 32 rows x 64 chunks(16B) = 2048 chunks, 8 per thread
        {
            const float* Wb = W + (size_t)k0 * Ntot + bn;
#pragma unroll
            for (int j = 0; j < 8; j++) {
                const int id  = tid + 256 * j;
                const int row = id >> 6;
                const int c   = id & 63;
                cp16(bbase + row * (BPITCH * 4) + c * 16,
                     Wb + (size_t)row * Ntot + c * 4);
            }
        }
    };

    float acc[4][8][4];
#pragma unroll
    for (int mi = 0; mi < 4; mi++)
#pragma unroll
        for (int ni = 0; ni < 8; ni++)
#pragma unroll
            for (int r = 0; r < 4; r++) acc[mi][ni][r] = 0.f;

    // prologue: stages 0,1
    fill(0, 0); CP_COMMIT();
    fill(1, 1); CP_COMMIT();

    const int NKT = CDIM / BK;   // 16
    for (int kt = 0; kt < NKT; kt++) {
        CP_WAIT1();
        __syncthreads();
        if (kt + 2 < NKT) fill((kt + 2) % 3, kt + 2);
        CP_COMMIT();

        const int st = kt % 3;
        const float* As = (const float*)(smem + st * STAGE);
        const float* Bs = (const float*)(smem + st * STAGE + ABYTES);

#pragma unroll
        for (int ks = 0; ks < 4; ks++) {
            const int c = ks * 8 + qc;
            uint32_t afr[4][4];
#pragma unroll
            for (int mi = 0; mi < 4; mi++) {
                const int r = wm + mi * 16 + qr;
                afr[mi][0] = f2tf32(As[r * APITCH + c]);
                afr[mi][1] = f2tf32(As[(r + 8) * APITCH + c]);
                afr[mi][2] = f2tf32(As[r * APITCH + c + 4]);
                afr[mi][3] = f2tf32(As[(r + 8) * APITCH + c + 4]);
            }
            uint32_t bfr[8][2];
#pragma unroll
            for (int ni = 0; ni < 8; ni++) {
                const int cc = wn + ni * 8 + qr;
                bfr[ni][0] = f2tf32(Bs[c * BPITCH + cc]);
                bfr[ni][1] = f2tf32(Bs[(ks * 8 + 4 + qc) * BPITCH + cc]);
            }
#pragma unroll
            for (int mi = 0; mi < 4; mi++)
#pragma unroll
                for (int ni = 0; ni < 8; ni++)
                    mma_tf32(acc[mi][ni], afr[mi][0], afr[mi][1], afr[mi][2], afr[mi][3],
                             bfr[ni][0], bfr[ni][1]);
        }
    }

    // epilogue: add bias, store
#pragma unroll
    for (int mi = 0; mi < 4; mi++) {
        const long row = bm + wm + mi * 16 + qr;
#pragma unroll
        for (int ni = 0; ni < 8; ni++) {
            const int col = bn + wn + ni * 8 + (qc << 1);
            const float b0v = __ldg(bias + col), b1v = __ldg(bias + col + 1);
            *(float2*)(C + (size_t)row * Ntot + col) =
                make_float2(acc[mi][ni][0] + b0v, acc[mi][ni][1] + b1v);
            *(float2*)(C + (size_t)(row + 8) * Ntot + col) =
                make_float2(acc[mi][ni][2] + b0v, acc[mi][ni][3] + b1v);
        }
    }
}

// ---------------- attention: one CTA per (window, head), 4 warps ----------------
__global__ void __launch_bounds__(128)
attn_kernel(const float* __restrict__ qkv, const float* __restrict__ mask,
            const float* __restrict__ biasg, float* __restrict__ outp) {
    __shared__ uint32_t qs[64][36];
    __shared__ uint32_t ksm[64][36];
    __shared__ uint32_t vsm[64][40];
    __shared__ uint32_t ps[4][16][68];
    __shared__ float    masks[64];

    const int b = blockIdx.x;
    const int h = blockIdx.y;
    const int tid  = threadIdx.x;
    const int lane = tid & 31;
    const int warp = tid >> 5;
    const int qr = lane >> 2;   // 0..7
    const int qc = lane & 3;    // 0..3

    const float* base = qkv + (size_t)b * NTOK * NQKV + h * DHEAD;
#pragma unroll
    for (int p = 0; p < 4; p++) {
        const int g = tid + 128 * p;
        const int t = g >> 3;
        const int c = (g & 7) << 2;
        const float* rowp = base + (size_t)t * NQKV + c;
        float4 qv = *(const float4*)(rowp);
        float4 kv = *(const float4*)(rowp + CDIM);
        float4 vv = *(const float4*)(rowp + 2 * CDIM);
        qs[t][c]     = f2tf32(qv.x); qs[t][c + 1] = f2tf32(qv.y);
        qs[t][c + 2] = f2tf32(qv.z); qs[t][c + 3] = f2tf32(qv.w);
        ksm[t][c]     = f2tf32(kv.x); ksm[t][c + 1] = f2tf32(kv.y);
        ksm[t][c + 2] = f2tf32(kv.z); ksm[t][c + 3] = f2tf32(kv.w);
        vsm[t][c]     = f2tf32(vv.x); vsm[t][c + 1] = f2tf32(vv.y);
        vsm[t][c + 2] = f2tf32(vv.z); vsm[t][c + 3] = f2tf32(vv.w);
    }
    if (tid < 64) masks[tid] = mask[(size_t)b * NTOK + tid];
    __syncthreads();

    const int i0 = warp * 16;
    float sacc[8][4];
#pragma unroll
    for (int nt = 0; nt < 8; nt++)
#pragma unroll
        for (int r = 0; r < 4; r++) sacc[nt][r] = 0.f;

#pragma unroll
    for (int ks = 0; ks < 4; ks++) {
        const int c = ks * 8 + qc;
        const uint32_t a0 = qs[i0 + qr][c];
        const uint32_t a1 = qs[i0 + 8 + qr][c];
        const uint32_t a2 = qs[i0 + qr][c + 4];
        const uint32_t a3 = qs[i0 + 8 + qr][c + 4];
#pragma unroll
        for (int nt = 0; nt < 8; nt++) {
            const uint32_t b0 = ksm[nt * 8 + qr][c];
            const uint32_t b1 = ksm[nt * 8 + qr][c + 4];
            mma_tf32(sacc[nt], a0, a1, a2, a3, b0, b1);
        }
    }

    const float scale = 0.17677669529663687f;   // 1/sqrt(32)
    const float* brow = biasg + h * (NTOK * NTOK);
    const int ra = i0 + qr;
    const int rb = ra + 8;

    float pv[8][4];
    float mA = -1e30f, mB = -1e30f;
#pragma unroll
    for (int nt = 0; nt < 8; nt++) {
        const int j = nt * 8 + (qc << 1);
        const float2 biA = *(const float2*)(brow + ra * 64 + j);
        const float2 biB = *(const float2*)(brow + rb * 64 + j);
        const float m0 = masks[j], m1 = masks[j + 1];
        pv[nt][0] = sacc[nt][0] * scale + biA.x + m0;
        pv[nt][1] = sacc[nt][1] * scale + biA.y + m1;
        pv[nt][2] = sacc[nt][2] * scale + biB.x + m0;
        pv[nt][3] = sacc[nt][3] * scale + biB.y + m1;
        mA = fmaxf(mA, fmaxf(pv[nt][0], pv[nt][1]));
        mB = fmaxf(mB, fmaxf(pv[nt][2], pv[nt][3]));
    }
#pragma unroll
    for (int off = 1; off <= 2; off <<= 1) {
        mA = fmaxf(mA, __shfl_xor_sync(0xffffffffu, mA, off));
        mB = fmaxf(mB, __shfl_xor_sync(0xffffffffu, mB, off));
    }
    float sA = 0.f, sB = 0.f;
#pragma unroll
    for (int nt = 0; nt < 8; nt++) {
        pv[nt][0] = __expf(pv[nt][0] - mA);
        pv[nt][1] = __expf(pv[nt][1] - mA);
        pv[nt][2] = __expf(pv[nt][2] - mB);
        pv[nt][3] = __expf(pv[nt][3] - mB);
        sA += pv[nt][0] + pv[nt][1];
        sB += pv[nt][2] + pv[nt][3];
    }
#pragma unroll
    for (int off = 1; off <= 2; off <<= 1) {
        sA += __shfl_xor_sync(0xffffffffu, sA, off);
        sB += __shfl_xor_sync(0xffffffffu, sB, off);
    }
    const float rAi = 1.f / sA;
    const float rBi = 1.f / sB;

#pragma unroll
    for (int nt = 0; nt < 8; nt++) {
        const int j = nt * 8 + (qc << 1);
        ps[warp][qr][j]         = f2tf32(pv[nt][0] * rAi);
        ps[warp][qr][j + 1]     = f2tf32(pv[nt][1] * rAi);
        ps[warp][qr + 8][j]     = f2tf32(pv[nt][2] * rBi);
        ps[warp][qr + 8][j + 1] = f2tf32(pv[nt][3] * rBi);
    }
    __syncwarp();

    float oacc[4][4];
#pragma unroll
    for (int nt = 0; nt < 4; nt++)
#pragma unroll
        for (int r = 0; r < 4; r++) oacc[nt][r] = 0.f;

#pragma unroll
    for (int ks = 0; ks < 8; ks++) {
        const int c = ks * 8 + qc;
        const uint32_t a0 = ps[warp][qr][c];
        const uint32_t a1 = ps[warp][qr + 8][c];
        const uint32_t a2 = ps[warp][qr][c + 4];
        const uint32_t a3 = ps[warp][qr + 8][c + 4];
#pragma unroll
        for (int nt = 0; nt < 4; nt++) {
            const uint32_t b0 = vsm[ks * 8 + qc][nt * 8 + qr];
            const uint32_t b1 = vsm[ks * 8 + 4 + qc][nt * 8 + qr];
            mma_tf32(oacc[nt], a0, a1, a2, a3, b0, b1);
        }
    }

    float* ob = outp + ((size_t)b * NTOK + i0) * CDIM + h * DHEAD;
#pragma unroll
    for (int nt = 0; nt < 4; nt++) {
        const int d = nt * 8 + (qc << 1);
        *(float2*)(ob + (size_t)qr * CDIM + d) = make_float2(oacc[nt][0], oacc[nt][1]);
        *(float2*)(ob + (size_t)(qr + 8) * CDIM + d) = make_float2(oacc[nt][2], oacc[nt][3]);
    }
}

// ---------------- launch ----------------
extern "C" void kernel_launch(void* const* d_in, const int* in_sizes, int n_in,
                              void* d_out, int out_size) {
    const float* x      = (const float*)d_in[0];
    const float* mask   = (const float*)d_in[1];
    const float* qkv_w  = (const float*)d_in[2];
    const float* qkv_b  = (const float*)d_in[3];
    const float* table  = (const float*)d_in[4];
    const float* proj_w = (const float*)d_in[5];
    const float* proj_b = (const float*)d_in[6];
    const int*   relidx = (const int*)d_in[7];
    float* out = (float*)d_out;

    float *p_qkv = nullptr, *p_attn = nullptr, *p_bias = nullptr;
    cudaGetSymbolAddress((void**)&p_qkv, g_qkv);
    cudaGetSymbolAddress((void**)&p_attn, g_attn);
    cudaGetSymbolAddress((void**)&p_bias, g_bias);

    cudaFuncSetAttribute(gemm_tf32_kernel,
                         cudaFuncAttributeMaxDynamicSharedMemorySize, GEMM_SMEM);

    // 1) relative-position bias gather -> [H, 64, 64]
    bias_kernel<<<HEADS, 256>>>(table, relidx, p_bias);

    // 2) QKV projection: [262144, 512] @ [512, 1536] + b
    gemm_tf32_kernel<<<dim3(NQKV / BN, MROWS / BM), 256, GEMM_SMEM>>>(
        x, qkv_w, qkv_b, p_qkv, NQKV);

    // 3) windowed attention per (window, head)
    attn_kernel<<<dim3(NW, HEADS), 128>>>(p_qkv, mask, p_bias, p_attn);

    // 4) output projection: [262144, 512] @ [512, 512] + b
    gemm_tf32_kernel<<<dim3(CDIM / BN, MROWS / BM), 256, GEMM_SMEM>>>(
        p_attn, proj_w, proj_b, out, CDIM);
}